// round 9
// baseline (speedup 1.0000x reference)
#include <cuda_runtime.h>
#include <cuda_bf16.h>
#include <cstdint>

// ---------------- problem constants ----------------
#define NN       2304
#define KDIM     128
#define KP       64              // packed bf16-pair count along K
#define NCOLS    14400
#define E0W      1060
#define EY_ELEMS (NN * NCOLS)    // 33177600
#define E0_ELEMS 1123600

// GEMM tiling
#define GM 256                   // rows per CTA (2 row-tiles of 16 per warp)
#define GN 64                    // cols per CTA
#define SPITCH 72                // smem row pitch (72%32==8 -> conflict-free)
#define NMG (NN / 16)            // 144 16-row fragment groups
#define FRAG_N (NMG * 8 * 32)    // uint4 fragments per plane = 36864

// ---------------- scratch (device globals, allocation-free) ----------------
__device__ float    g_eta[NN];
__device__ uint32_t g_hhi[NN * KP];
__device__ uint32_t g_hlo[NN * KP];
__device__ __align__(16) uint4 g_fragHi[FRAG_N];
__device__ __align__(16) uint4 g_fragLo[FRAG_N];
__device__ uint32_t g_Whi[KP * NCOLS];
__device__ uint32_t g_Wlo[KP * NCOLS];
__device__ int      g_tbl[NCOLS];         // packed (tij<<9 | ab) gather table
__device__ float    g_TreAcc[NN];         // fused-esum partial sums
__device__ float    g_TimAcc[NN];
__device__ __align__(16) float g_Ey[EY_ELEMS];   // fallback output modes only
__device__ float    g_Tre[NN];            // finalized T (for fallback pack)
__device__ float    g_Tim[NN];
__device__ float    g_zero[2 * E0_ELEMS]; // universal null-input fallback

// ---------------------------------------------------------------------------
// helpers
// ---------------------------------------------------------------------------
__device__ __forceinline__ void bf16_split_pack(float x0, float x1,
                                                uint32_t& hi, uint32_t& lo)
{
    __nv_bfloat16 h0 = __float2bfloat16_rn(x0);
    __nv_bfloat16 h1 = __float2bfloat16_rn(x1);
    hi = (uint32_t)__bfloat16_as_ushort(h0)
       | ((uint32_t)__bfloat16_as_ushort(h1) << 16);
    __nv_bfloat16 l0 = __float2bfloat16_rn(x0 - __bfloat162float(h0));
    __nv_bfloat16 l1 = __float2bfloat16_rn(x1 - __bfloat162float(h1));
    lo = (uint32_t)__bfloat16_as_ushort(l0)
       | ((uint32_t)__bfloat16_as_ushort(l1) << 16);
}

// D += A(16x16 bf16) * B(16x8 bf16), fp32 accum. sm_80+ HMMA.
__device__ __forceinline__ void mma_bf16(float* c, const uint4& a,
                                         uint32_t b0, uint32_t b1)
{
    asm volatile(
        "mma.sync.aligned.m16n8k16.row.col.f32.bf16.bf16.f32 "
        "{%0,%1,%2,%3}, {%4,%5,%6,%7}, {%8,%9}, {%0,%1,%2,%3};\n"
        : "+f"(c[0]), "+f"(c[1]), "+f"(c[2]), "+f"(c[3])
        : "r"(a.x), "r"(a.y), "r"(a.z), "r"(a.w), "r"(b0), "r"(b1));
}

// ---------------------------------------------------------------------------
// Kernel 0: gather table + zero the T accumulators.
// ---------------------------------------------------------------------------
__global__ void prep_kernel()
{
    int e = blockIdx.x * 256 + threadIdx.x;
    if (e < NN) { g_TreAcc[e] = 0.f; g_TimAcc[e] = 0.f; }
    if (e >= NCOLS) return;
    int y = e / 120, x = e - y * 120;
    int i = y / 20, a = y - i * 20;
    int j = x / 20, b = x - j * 20;
    int tij = (i * 20) * E0W + j * 20;
    g_tbl[e] = (tij << 9) | (a * 20 + b);
}

// ---------------------------------------------------------------------------
// Kernel 1: the two small MLPs; also emits split-bf16 packed h.
// ---------------------------------------------------------------------------
__global__ void __launch_bounds__(128) mlp_kernel(
    const float* hs,
    const float* nW0, const float* nb0, const float* nW1, const float* nb1,
    const float* nW2, const float* nb2,
    const float* eW0, const float* eb0, const float* eW1, const float* eb1)
{
    const float* HS  = hs  ? hs  : g_zero;
    const float* NW0 = nW0 ? nW0 : g_zero;  const float* NB0 = nb0 ? nb0 : g_zero;
    const float* NW1 = nW1 ? nW1 : g_zero;  const float* NB1 = nb1 ? nb1 : g_zero;
    const float* NW2 = nW2 ? nW2 : g_zero;  const float* NB2 = nb2 ? nb2 : g_zero;
    const float* EW0 = eW0 ? eW0 : g_zero;  const float* EB0 = eb0 ? eb0 : g_zero;
    const float* EW1 = eW1 ? eW1 : g_zero;  const float* EB1 = eb1 ? eb1 : g_zero;

    int p = blockIdx.x, j = threadIdx.x;
    float x = HS[p];
    __shared__ float s1[KDIM], s2[KDIM];

    // ---- neff branch ----
    s1[j] = fmaxf(fmaf(x, NW0[j], NB0[j]), 0.0f);
    __syncthreads();
    float acc = NB1[j];
#pragma unroll 8
    for (int k = 0; k < KDIM; ++k) acc = fmaf(s1[k], NW1[k * KDIM + j], acc);
    float h2 = fmaxf(acc, 0.0f);
    __syncthreads();
    s2[j] = h2 * NW2[j];
    __syncthreads();
    for (int off = 64; off > 0; off >>= 1) {
        if (j < off) s2[j] += s2[j + off];
        __syncthreads();
    }
    if (j == 0) {
        float neff = s2[0] + NB2[0];
        g_eta[p] = neff / (neff + 1.0f);   // N0 = 1
    }
    __syncthreads();

    // ---- enn branch ----
    s1[j] = fmaxf(fmaf(x, EW0[j], EB0[j]), 0.0f);
    __syncthreads();
    acc = EB1[j];
#pragma unroll 8
    for (int k = 0; k < KDIM; ++k) acc = fmaf(s1[k], EW1[k * KDIM + j], acc);
    float hval = fmaxf(acc, 0.0f);
    __syncthreads();
    s2[j] = hval;
    __syncthreads();
    if (j < KP) {
        uint32_t hi, lo;
        bf16_split_pack(s2[2 * j], s2[2 * j + 1], hi, lo);
        g_hhi[p * KP + j] = hi;
        g_hlo[p * KP + j] = lo;
    }
}

// ---------------------------------------------------------------------------
// Kernel 1b: split-pack eW2 into K-pair planes.
// ---------------------------------------------------------------------------
__global__ void __launch_bounds__(256) wpack_kernel(const float* W_in)
{
    const float* W = W_in ? W_in : g_zero;
    int id = blockIdx.x * 256 + threadIdx.x;
    if (id >= KP * NCOLS) return;
    int kp = id / NCOLS, c = id - kp * NCOLS;
    float x0 = W[(2 * kp) * NCOLS + c];
    float x1 = W[(2 * kp + 1) * NCOLS + c];
    bf16_split_pack(x0, x1, g_Whi[id], g_Wlo[id]);
}

// ---------------------------------------------------------------------------
// Kernel 1c: swizzle h into A-fragment order (proven round 8).
// ---------------------------------------------------------------------------
__global__ void __launch_bounds__(256) hfrag_kernel()
{
    int id = blockIdx.x * 256 + threadIdx.x;
    if (id >= 2 * FRAG_N) return;
    int plane = id / FRAG_N;
    int r = id - plane * FRAG_N;
    int lane = r & 31;
    int ks = (r >> 5) & 7;
    int mg = r >> 8;
    int qrow = lane >> 2, qk = lane & 3;
    int row = mg * 16 + qrow;
    int kp  = ks * 8 + qk;
    const uint32_t* src = plane ? g_hlo : g_hhi;
    uint4 v;
    v.x = src[row * KP + kp];
    v.y = src[(row + 8) * KP + kp];
    v.z = src[row * KP + kp + 4];
    v.w = src[(row + 8) * KP + kp + 4];
    (plane ? g_fragLo : g_fragHi)[r] = v;
}

// ---------------------------------------------------------------------------
// Kernel 2: HMMA bf16 split GEMM with FUSED T-reduction epilogue.
// Ey = h @ W + bias -> eyout; simultaneously accumulates
// sum_e Ey[p,e]*E0_slice[p,e] into g_TreAcc/g_TimAcc via quad-reduce +
// one atomicAdd per row per CTA.
// ---------------------------------------------------------------------------
__global__ void __launch_bounds__(256, 2) gemm_mma(
    const float* bias_in, float* eyout,
    const float* E0r_in, const float* E0i_in, int stride)
{
    const float* bias = bias_in ? bias_in : g_zero;
    const float* E0r  = E0r_in  ? E0r_in  : g_zero;
    const float* E0i  = E0i_in  ? E0i_in  : g_zero;
    float* o = eyout ? eyout : g_Ey;

    __shared__ uint32_t sBhi[KP * SPITCH];
    __shared__ uint32_t sBlo[KP * SPITCH];

    const int c0 = blockIdx.x * GN;
    const int p0 = blockIdx.y * GM;
    const int t = threadIdx.x;
    const int w = t >> 5, lane = t & 31;

    // stage B tile (vectorized)
    {
        const uint4* srcH = (const uint4*)(g_Whi + c0);
        const uint4* srcL = (const uint4*)(g_Wlo + c0);
        for (int i = t; i < KP * 16; i += 256) {
            int kp = i >> 4, qc = i & 15;
            uint4 vh = srcH[kp * (NCOLS / 4) + qc];
            uint4 vl = srcL[kp * (NCOLS / 4) + qc];
            *(uint4*)&sBhi[kp * SPITCH + qc * 4] = vh;
            *(uint4*)&sBlo[kp * SPITCH + qc * 4] = vl;
        }
    }
    __syncthreads();

    const int r0   = p0 + w * 32;
    const int qrow = lane >> 2;   // 0..7
    const int qk   = lane & 3;    // 0..3
    const int mg0  = r0 >> 4;

    float acc[2][8][4];
#pragma unroll
    for (int u = 0; u < 2; ++u)
#pragma unroll
        for (int s = 0; s < 8; ++s)
#pragma unroll
            for (int q = 0; q < 4; ++q) acc[u][s][q] = 0.0f;

    for (int ks = 0; ks < 8; ++ks) {
        const int kb = ks * 8;
        uint4 ah0 = g_fragHi[(mg0 * 8 + ks) * 32 + lane];
        uint4 al0 = g_fragLo[(mg0 * 8 + ks) * 32 + lane];
        uint4 ah1 = g_fragHi[((mg0 + 1) * 8 + ks) * 32 + lane];
        uint4 al1 = g_fragLo[((mg0 + 1) * 8 + ks) * 32 + lane];

        const uint32_t* rh0 = &sBhi[(kb + qk) * SPITCH + qrow];
        const uint32_t* rh1 = &sBhi[(kb + qk + 4) * SPITCH + qrow];
        const uint32_t* rl0 = &sBlo[(kb + qk) * SPITCH + qrow];
        const uint32_t* rl1 = &sBlo[(kb + qk + 4) * SPITCH + qrow];

#pragma unroll
        for (int s = 0; s < 8; ++s) {
            uint32_t bh0 = rh0[s * 8];
            uint32_t bh1 = rh1[s * 8];
            uint32_t bl0 = rl0[s * 8];
            uint32_t bl1 = rl1[s * 8];
            mma_bf16(acc[0][s], ah0, bh0, bh1);
            mma_bf16(acc[0][s], ah0, bl0, bl1);
            mma_bf16(acc[0][s], al0, bh0, bh1);
            mma_bf16(acc[1][s], ah1, bh0, bh1);
            mma_bf16(acc[1][s], ah1, bl0, bl1);
            mma_bf16(acc[1][s], al1, bh0, bh1);
        }
    }

    // ---- fused epilogue: store Ey AND accumulate T partials ----
    // rows handled by this thread: [u*2+half] -> r0 + 16u + qrow + 8*half
    int rows[4];
    rows[0] = r0 + qrow;        rows[1] = r0 + qrow + 8;
    rows[2] = r0 + 16 + qrow;   rows[3] = r0 + 24 + qrow;
    int basev[4], limv[4];
#pragma unroll
    for (int i = 0; i < 4; ++i) {
        int f0 = rows[i] * 400;
        int rp = f0 / 960;
        int cp = f0 - rp * 960;
        basev[i] = rp * E0W + cp;
        limv[i]  = 960 - cp;
    }
    float tre[4] = {0.f, 0.f, 0.f, 0.f};
    float tim[4] = {0.f, 0.f, 0.f, 0.f};

#pragma unroll
    for (int s = 0; s < 8; ++s) {
        int c = c0 + s * 8 + qk * 2;
        float b0 = bias[c], b1 = bias[c + 1];
        int tb0 = g_tbl[c], tb1 = g_tbl[c + 1];
        int ab0 = tb0 & 511, ab1 = tb1 & 511;
        int t0 = tb0 >> 9,   t1 = tb1 >> 9;
#pragma unroll
        for (int u = 0; u < 2; ++u) {
            float v0 = acc[u][s][0] + b0;
            float v1 = acc[u][s][1] + b1;
            float v2 = acc[u][s][2] + b0;
            float v3 = acc[u][s][3] + b1;
            size_t rA = (size_t)rows[u * 2];
            size_t rB = (size_t)rows[u * 2 + 1];
            *(float2*)&o[rA * NCOLS + c] = make_float2(v0, v1);
            *(float2*)&o[rB * NCOLS + c] = make_float2(v2, v3);

            int iA0 = basev[u*2]   + t0 + ab0 + ((ab0 >= limv[u*2])   ? 100 : 0);
            int iA1 = basev[u*2]   + t1 + ab1 + ((ab1 >= limv[u*2])   ? 100 : 0);
            int iB0 = basev[u*2+1] + t0 + ab0 + ((ab0 >= limv[u*2+1]) ? 100 : 0);
            int iB1 = basev[u*2+1] + t1 + ab1 + ((ab1 >= limv[u*2+1]) ? 100 : 0);
            tre[u*2]   = fmaf(v0, E0r[iA0 * stride], tre[u*2]);
            tim[u*2]   = fmaf(v0, E0i[iA0 * stride], tim[u*2]);
            tre[u*2]   = fmaf(v1, E0r[iA1 * stride], tre[u*2]);
            tim[u*2]   = fmaf(v1, E0i[iA1 * stride], tim[u*2]);
            tre[u*2+1] = fmaf(v2, E0r[iB0 * stride], tre[u*2+1]);
            tim[u*2+1] = fmaf(v2, E0i[iB0 * stride], tim[u*2+1]);
            tre[u*2+1] = fmaf(v3, E0r[iB1 * stride], tre[u*2+1]);
            tim[u*2+1] = fmaf(v3, E0i[iB1 * stride], tim[u*2+1]);
        }
    }

    // quad-reduce (lanes 4q..4q+3 share the same rows), then one atomic/row
#pragma unroll
    for (int i = 0; i < 4; ++i) {
        tre[i] += __shfl_xor_sync(0xffffffffu, tre[i], 1);
        tre[i] += __shfl_xor_sync(0xffffffffu, tre[i], 2);
        tim[i] += __shfl_xor_sync(0xffffffffu, tim[i], 1);
        tim[i] += __shfl_xor_sync(0xffffffffu, tim[i], 2);
    }
    if (qk == 0) {
#pragma unroll
        for (int i = 0; i < 4; ++i) {
            atomicAdd(&g_TreAcc[rows[i]], tre[i]);
            atomicAdd(&g_TimAcc[rows[i]], tim[i]);
        }
    }
}

// ---------------------------------------------------------------------------
// Kernel 3: finalize T = 0.005 * eta * acc; write T.real to out (fast mode).
// ---------------------------------------------------------------------------
__global__ void finalize_kernel(float* outT)
{
    int p = blockIdx.x * 256 + threadIdx.x;
    if (p >= NN) return;
    float s = 0.005f * g_eta[p];
    float tre = s * g_TreAcc[p];
    float tim = s * g_TimAcc[p];
    g_Tre[p] = tre;
    g_Tim[p] = tim;
    if (outT) outT[p] = tre;
}

// ---------------------------------------------------------------------------
// Kernel 4 (fallback modes only): scalar-float pack, never exceeds cnt.
// ---------------------------------------------------------------------------
__global__ void pack_kernel(float* out, long long cnt, int mode)
{
    long long i = (long long)blockIdx.x * 256 + threadIdx.x;
    if (i >= cnt) return;
    float v = 0.f;
    if (mode == 1 || mode == 5) {
        if (i < EY_ELEMS) v = g_Ey[i];
        else {
            long long q = i - EY_ELEMS;
            if (q < 2 * NN) v = (q & 1) ? g_Tim[q >> 1] : g_Tre[q >> 1];
        }
    } else if (mode == 2) v = g_Ey[i];
    else if (mode == 3) v = (i & 1) ? g_Tim[i >> 1] : g_Tre[i >> 1];
    else if (mode == 4) v = g_Tre[i];
    out[i] = v;
}

// ---------------------------------------------------------------------------
extern "C" void kernel_launch(void* const* d_in, const int* in_sizes, int n_in,
                              void* d_out, int out_size)
{
    if (n_in > 64) n_in = 64;
    bool used[64];
    for (int i = 0; i < 64; ++i) used[i] = false;
    auto take = [&](int sz) -> const float* {
        for (int i = 0; i < n_in; ++i)
            if (!used[i] && in_sizes[i] == sz) {
                used[i] = true;
                return (const float*)d_in[i];
            }
        return nullptr;
    };

    const float* hs = take(2304);
    const float* E0r; const float* E0i; int e0stride;
    {
        const float* a = take(E0_ELEMS);
        if (a) { E0r = a; E0i = take(E0_ELEMS); e0stride = 1; }
        else {
            const float* c1 = take(2 * E0_ELEMS);
            const float* c2 = take(2 * E0_ELEMS);
            if (c1 && c2)      { E0r = c1; E0i = c2;     e0stride = 2; }
            else if (c1)       { E0r = c1; E0i = c1 + 1; e0stride = 2; }
            else               { E0r = nullptr; E0i = nullptr; e0stride = 1; }
        }
    }
    const float* nW0 = take(128);
    const float* nb0 = take(128);
    const float* nW1 = take(16384);
    const float* nb1 = take(128);
    const float* nW2 = take(128);
    const float* nb2 = take(1);
    const float* eW0 = take(128);
    const float* eb0 = take(128);
    const float* eW1 = take(16384);
    const float* eb1 = take(128);
    const float* eW2 = take(1843200);
    const float* eb2 = take(14400);
    float* out = (float*)d_out;

    const bool fast = (out_size == EY_ELEMS + NN);   // confirmed in round 4

    prep_kernel<<<(NCOLS + 255) / 256, 256>>>();     // also zeroes T accums
    mlp_kernel<<<NN, 128>>>(hs, nW0, nb0, nW1, nb1, nW2, nb2,
                            eW0, eb0, eW1, eb1);
    wpack_kernel<<<(KP * NCOLS + 255) / 256, 256>>>(eW2);
    hfrag_kernel<<<(2 * FRAG_N + 255) / 256, 256>>>();

    gemm_mma<<<dim3(NCOLS / GN, NN / GM), 256>>>(
        eb2, fast ? out : nullptr, E0r, E0i, e0stride);

    finalize_kernel<<<(NN + 255) / 256, 256>>>(fast ? out + EY_ELEMS : nullptr);

    if (!fast) {
        long long cnt; int mode;
        if      (out_size == EY_ELEMS + 2 * NN) { mode = 1; cnt = out_size; }
        else if (out_size == EY_ELEMS)          { mode = 2; cnt = out_size; }
        else if (out_size == 2 * NN)            { mode = 3; cnt = out_size; }
        else if (out_size == NN)                { mode = 4; cnt = out_size; }
        else { mode = 5; cnt = out_size / 4; }
        if (cnt < 1) cnt = 1;
        pack_kernel<<<(unsigned)((cnt + 255) / 256), 256>>>(out, cnt, mode);
    }
}

// round 10
// speedup vs baseline: 1.0409x; 1.0409x over previous
#include <cuda_runtime.h>
#include <cuda_bf16.h>
#include <cstdint>

// ---------------- problem constants ----------------
#define NN       2304
#define KDIM     128
#define KP       64              // packed bf16-pair count along K
#define NCOLS    14400
#define E0W      1060
#define EY_ELEMS (NN * NCOLS)    // 33177600
#define E0_ELEMS 1123600

// GEMM tiling (round-8 proven)
#define GM 256                   // rows per CTA (2 row-tiles of 16 per warp)
#define GN 64                    // cols per CTA
#define SPITCH 72                // smem row pitch (72%32==8 -> conflict-free)
#define NMG (NN / 16)            // 144 16-row fragment groups
#define FRAG_N (NMG * 8 * 32)    // uint4 fragments per plane = 36864

// ---------------- scratch (device globals, allocation-free) ----------------
__device__ float    g_eta[NN];
__device__ uint32_t g_hhi[NN * KP];
__device__ uint32_t g_hlo[NN * KP];
__device__ __align__(16) uint4 g_fragHi[FRAG_N];
__device__ __align__(16) uint4 g_fragLo[FRAG_N];
__device__ uint32_t g_Whi[KP * NCOLS];
__device__ uint32_t g_Wlo[KP * NCOLS];
__device__ __align__(16) int g_tbl[NCOLS];       // packed (tij<<9 | ab) table
__device__ __align__(16) float g_Ey[EY_ELEMS];   // fallback output modes only
__device__ float    g_Tre[NN];
__device__ float    g_Tim[NN];
__device__ float    g_zero[2 * E0_ELEMS];        // universal null-input fallback

// ---------------------------------------------------------------------------
// helpers
// ---------------------------------------------------------------------------
__device__ __forceinline__ void bf16_split_pack(float x0, float x1,
                                                uint32_t& hi, uint32_t& lo)
{
    __nv_bfloat16 h0 = __float2bfloat16_rn(x0);
    __nv_bfloat16 h1 = __float2bfloat16_rn(x1);
    hi = (uint32_t)__bfloat16_as_ushort(h0)
       | ((uint32_t)__bfloat16_as_ushort(h1) << 16);
    __nv_bfloat16 l0 = __float2bfloat16_rn(x0 - __bfloat162float(h0));
    __nv_bfloat16 l1 = __float2bfloat16_rn(x1 - __bfloat162float(h1));
    lo = (uint32_t)__bfloat16_as_ushort(l0)
       | ((uint32_t)__bfloat16_as_ushort(l1) << 16);
}

// D += A(16x16 bf16) * B(16x8 bf16), fp32 accum. sm_80+ HMMA.
__device__ __forceinline__ void mma_bf16(float* c, const uint4& a,
                                         uint32_t b0, uint32_t b1)
{
    asm volatile(
        "mma.sync.aligned.m16n8k16.row.col.f32.bf16.bf16.f32 "
        "{%0,%1,%2,%3}, {%4,%5,%6,%7}, {%8,%9}, {%0,%1,%2,%3};\n"
        : "+f"(c[0]), "+f"(c[1]), "+f"(c[2]), "+f"(c[3])
        : "r"(a.x), "r"(a.y), "r"(a.z), "r"(a.w), "r"(b0), "r"(b1));
}

// ---------------------------------------------------------------------------
// Kernel 0: build the p-independent gather table for esum.
// ---------------------------------------------------------------------------
__global__ void prep_kernel()
{
    int e = blockIdx.x * 256 + threadIdx.x;
    if (e >= NCOLS) return;
    int y = e / 120, x = e - y * 120;
    int i = y / 20, a = y - i * 20;
    int j = x / 20, b = x - j * 20;
    int tij = (i * 20) * E0W + j * 20;
    g_tbl[e] = (tij << 9) | (a * 20 + b);
}

// ---------------------------------------------------------------------------
// Kernel 1: the two small MLPs; also emits split-bf16 packed h.
// ---------------------------------------------------------------------------
__global__ void __launch_bounds__(128) mlp_kernel(
    const float* hs,
    const float* nW0, const float* nb0, const float* nW1, const float* nb1,
    const float* nW2, const float* nb2,
    const float* eW0, const float* eb0, const float* eW1, const float* eb1)
{
    const float* HS  = hs  ? hs  : g_zero;
    const float* NW0 = nW0 ? nW0 : g_zero;  const float* NB0 = nb0 ? nb0 : g_zero;
    const float* NW1 = nW1 ? nW1 : g_zero;  const float* NB1 = nb1 ? nb1 : g_zero;
    const float* NW2 = nW2 ? nW2 : g_zero;  const float* NB2 = nb2 ? nb2 : g_zero;
    const float* EW0 = eW0 ? eW0 : g_zero;  const float* EB0 = eb0 ? eb0 : g_zero;
    const float* EW1 = eW1 ? eW1 : g_zero;  const float* EB1 = eb1 ? eb1 : g_zero;

    int p = blockIdx.x, j = threadIdx.x;
    float x = HS[p];
    __shared__ float s1[KDIM], s2[KDIM];

    // ---- neff branch ----
    s1[j] = fmaxf(fmaf(x, NW0[j], NB0[j]), 0.0f);
    __syncthreads();
    float acc = NB1[j];
#pragma unroll 8
    for (int k = 0; k < KDIM; ++k) acc = fmaf(s1[k], NW1[k * KDIM + j], acc);
    float h2 = fmaxf(acc, 0.0f);
    __syncthreads();
    s2[j] = h2 * NW2[j];
    __syncthreads();
    for (int off = 64; off > 0; off >>= 1) {
        if (j < off) s2[j] += s2[j + off];
        __syncthreads();
    }
    if (j == 0) {
        float neff = s2[0] + NB2[0];
        g_eta[p] = neff / (neff + 1.0f);   // N0 = 1
    }
    __syncthreads();

    // ---- enn branch ----
    s1[j] = fmaxf(fmaf(x, EW0[j], EB0[j]), 0.0f);
    __syncthreads();
    acc = EB1[j];
#pragma unroll 8
    for (int k = 0; k < KDIM; ++k) acc = fmaf(s1[k], EW1[k * KDIM + j], acc);
    float hval = fmaxf(acc, 0.0f);
    __syncthreads();
    s2[j] = hval;
    __syncthreads();
    if (j < KP) {
        uint32_t hi, lo;
        bf16_split_pack(s2[2 * j], s2[2 * j + 1], hi, lo);
        g_hhi[p * KP + j] = hi;
        g_hlo[p * KP + j] = lo;
    }
}

// ---------------------------------------------------------------------------
// Kernel 1b: split-pack eW2 into K-pair planes.
// ---------------------------------------------------------------------------
__global__ void __launch_bounds__(256) wpack_kernel(const float* W_in)
{
    const float* W = W_in ? W_in : g_zero;
    int id = blockIdx.x * 256 + threadIdx.x;
    if (id >= KP * NCOLS) return;
    int kp = id / NCOLS, c = id - kp * NCOLS;
    float x0 = W[(2 * kp) * NCOLS + c];
    float x1 = W[(2 * kp + 1) * NCOLS + c];
    bf16_split_pack(x0, x1, g_Whi[id], g_Wlo[id]);
}

// ---------------------------------------------------------------------------
// Kernel 1c: swizzle h into A-fragment order, staged through smem.
// One block per 16-row group mg. Coalesced loads (16 rows x 64 kp,
// contiguous) + padded-smem (pitch 65, conflict-free) fragment assembly +
// coalesced uint4 writes. Fragment values bit-identical to round 8.
// ---------------------------------------------------------------------------
#define HPITCH 65
__global__ void __launch_bounds__(256) hfrag_kernel()
{
    __shared__ uint32_t shi[16 * HPITCH];
    __shared__ uint32_t slo[16 * HPITCH];

    const int mg = blockIdx.x;
    const int t  = threadIdx.x;

    // stage 16 rows x 64 kp of hi/lo (coalesced: 1024 consecutive u32 each)
    const uint32_t* srcH = g_hhi + mg * 16 * KP;
    const uint32_t* srcL = g_hlo + mg * 16 * KP;
    for (int i = t; i < 16 * KP; i += 256) {
        int r = i >> 6, k = i & 63;
        shi[r * HPITCH + k] = srcH[i];
        slo[r * HPITCH + k] = srcL[i];
    }
    __syncthreads();

    // assemble fragments: thread t -> (ks = t>>5, lane = t&31), both planes
    const int lane = t & 31;
    const int ks   = t >> 5;
    const int qrow = lane >> 2, qk = lane & 3;
    const int kp   = ks * 8 + qk;
    const int r    = (mg * 8 + ks) * 32 + lane;

    uint4 vh, vl;
    vh.x = shi[qrow * HPITCH + kp];
    vh.y = shi[(qrow + 8) * HPITCH + kp];
    vh.z = shi[qrow * HPITCH + kp + 4];
    vh.w = shi[(qrow + 8) * HPITCH + kp + 4];
    vl.x = slo[qrow * HPITCH + kp];
    vl.y = slo[(qrow + 8) * HPITCH + kp];
    vl.z = slo[qrow * HPITCH + kp + 4];
    vl.w = slo[(qrow + 8) * HPITCH + kp + 4];
    g_fragHi[r] = vh;
    g_fragLo[r] = vl;
}

// ---------------------------------------------------------------------------
// Kernel 2: HMMA bf16 split GEMM (round-8 proven, unfused).
// ---------------------------------------------------------------------------
__global__ void __launch_bounds__(256) gemm_mma(
    const float* bias_in, float* eyout)
{
    const float* bias = bias_in ? bias_in : g_zero;
    float* o = eyout ? eyout : g_Ey;

    __shared__ uint32_t sBhi[KP * SPITCH];
    __shared__ uint32_t sBlo[KP * SPITCH];

    const int c0 = blockIdx.x * GN;
    const int p0 = blockIdx.y * GM;
    const int t = threadIdx.x;
    const int w = t >> 5, lane = t & 31;

    // stage B tile (vectorized)
    {
        const uint4* srcH = (const uint4*)(g_Whi + c0);
        const uint4* srcL = (const uint4*)(g_Wlo + c0);
        for (int i = t; i < KP * 16; i += 256) {
            int kp = i >> 4, qc = i & 15;
            uint4 vh = srcH[kp * (NCOLS / 4) + qc];
            uint4 vl = srcL[kp * (NCOLS / 4) + qc];
            *(uint4*)&sBhi[kp * SPITCH + qc * 4] = vh;
            *(uint4*)&sBlo[kp * SPITCH + qc * 4] = vl;
        }
    }
    __syncthreads();

    const int r0   = p0 + w * 32;
    const int qrow = lane >> 2;
    const int qk   = lane & 3;
    const int mg0  = r0 >> 4;

    float acc[2][8][4];
#pragma unroll
    for (int u = 0; u < 2; ++u)
#pragma unroll
        for (int s = 0; s < 8; ++s)
#pragma unroll
            for (int q = 0; q < 4; ++q) acc[u][s][q] = 0.0f;

    for (int ks = 0; ks < 8; ++ks) {
        const int kb = ks * 8;
        uint4 ah0 = g_fragHi[(mg0 * 8 + ks) * 32 + lane];
        uint4 al0 = g_fragLo[(mg0 * 8 + ks) * 32 + lane];
        uint4 ah1 = g_fragHi[((mg0 + 1) * 8 + ks) * 32 + lane];
        uint4 al1 = g_fragLo[((mg0 + 1) * 8 + ks) * 32 + lane];

        const uint32_t* rh0 = &sBhi[(kb + qk) * SPITCH + qrow];
        const uint32_t* rh1 = &sBhi[(kb + qk + 4) * SPITCH + qrow];
        const uint32_t* rl0 = &sBlo[(kb + qk) * SPITCH + qrow];
        const uint32_t* rl1 = &sBlo[(kb + qk + 4) * SPITCH + qrow];

#pragma unroll
        for (int s = 0; s < 8; ++s) {
            uint32_t bh0 = rh0[s * 8];
            uint32_t bh1 = rh1[s * 8];
            uint32_t bl0 = rl0[s * 8];
            uint32_t bl1 = rl1[s * 8];
            mma_bf16(acc[0][s], ah0, bh0, bh1);
            mma_bf16(acc[0][s], ah0, bl0, bl1);
            mma_bf16(acc[0][s], al0, bh0, bh1);
            mma_bf16(acc[1][s], ah1, bh0, bh1);
            mma_bf16(acc[1][s], ah1, bl0, bl1);
            mma_bf16(acc[1][s], al1, bh0, bh1);
        }
    }

    // epilogue: bias + direct coalesced float2 stores (two row tiles)
#pragma unroll
    for (int s = 0; s < 8; ++s) {
        int c = c0 + s * 8 + qk * 2;
        float b0 = bias[c], b1 = bias[c + 1];
#pragma unroll
        for (int u = 0; u < 2; ++u) {
            size_t r = (size_t)(r0 + 16 * u + qrow);
            float2 v0 = make_float2(acc[u][s][0] + b0, acc[u][s][1] + b1);
            float2 v1 = make_float2(acc[u][s][2] + b0, acc[u][s][3] + b1);
            *(float2*)&o[r * NCOLS + c]       = v0;
            *(float2*)&o[(r + 8) * NCOLS + c] = v1;
        }
    }
}

// ---------------------------------------------------------------------------
// Kernel 3: T[p] = 0.005 * eta[p] * sum_e Ey[p,e] * E0_slice[p,e]
// Vectorized: float4 Ey stream + int4 table; scalar L2-resident E0 gathers.
// ---------------------------------------------------------------------------
__global__ void __launch_bounds__(256) esum_kernel(
    const float* ey_in, const float* E0r_in, const float* E0i_in,
    int stride, float* outT)
{
    const float* ey  = ey_in  ? ey_in  : g_Ey;
    const float* E0r = E0r_in ? E0r_in : g_zero;
    const float* E0i = E0i_in ? E0i_in : g_zero;

    const int p = blockIdx.x, t = threadIdx.x;
    const int f0  = p * 400;
    const int r0p = f0 / 960;
    const int c0p = f0 - r0p * 960;
    const int base = r0p * E0W + c0p;
    const int lim  = 960 - c0p;        // wrap when ab >= lim

    float sre = 0.f, sim = 0.f;
    const float4* ey4  = (const float4*)(ey + (size_t)p * NCOLS);
    const int4*   tbl4 = (const int4*)g_tbl;

    for (int q = t; q < NCOLS / 4; q += 256) {   // 3600 float4 groups
        int4   tb = tbl4[q];
        float4 g  = ey4[q];

        int ab0 = tb.x & 511;
        int i0  = base + (tb.x >> 9) + ab0 + ((ab0 >= lim) ? 100 : 0);
        int ab1 = tb.y & 511;
        int i1  = base + (tb.y >> 9) + ab1 + ((ab1 >= lim) ? 100 : 0);
        int ab2 = tb.z & 511;
        int i2  = base + (tb.z >> 9) + ab2 + ((ab2 >= lim) ? 100 : 0);
        int ab3 = tb.w & 511;
        int i3  = base + (tb.w >> 9) + ab3 + ((ab3 >= lim) ? 100 : 0);

        sre = fmaf(g.x, E0r[i0 * stride], sre);
        sim = fmaf(g.x, E0i[i0 * stride], sim);
        sre = fmaf(g.y, E0r[i1 * stride], sre);
        sim = fmaf(g.y, E0i[i1 * stride], sim);
        sre = fmaf(g.z, E0r[i2 * stride], sre);
        sim = fmaf(g.z, E0i[i2 * stride], sim);
        sre = fmaf(g.w, E0r[i3 * stride], sre);
        sim = fmaf(g.w, E0i[i3 * stride], sim);
    }

#pragma unroll
    for (int off = 16; off > 0; off >>= 1) {
        sre += __shfl_down_sync(0xffffffffu, sre, off);
        sim += __shfl_down_sync(0xffffffffu, sim, off);
    }
    __shared__ float wr[8], wi[8];
    if ((t & 31) == 0) { wr[t >> 5] = sre; wi[t >> 5] = sim; }
    __syncthreads();
    if (t == 0) {
        float tre = 0.f, tim = 0.f;
        for (int q = 0; q < 8; ++q) { tre += wr[q]; tim += wi[q]; }
        float s = 0.005f * g_eta[p];   // 2*C_EPSILON*dx*dx
        g_Tre[p] = s * tre;
        g_Tim[p] = s * tim;
        if (outT) outT[p] = s * tre;
    }
}

// ---------------------------------------------------------------------------
// Kernel 4 (fallback modes only): scalar-float pack, never exceeds cnt.
// ---------------------------------------------------------------------------
__global__ void pack_kernel(float* out, long long cnt, int mode)
{
    long long i = (long long)blockIdx.x * 256 + threadIdx.x;
    if (i >= cnt) return;
    float v = 0.f;
    if (mode == 1 || mode == 5) {
        if (i < EY_ELEMS) v = g_Ey[i];
        else {
            long long q = i - EY_ELEMS;
            if (q < 2 * NN) v = (q & 1) ? g_Tim[q >> 1] : g_Tre[q >> 1];
        }
    } else if (mode == 2) v = g_Ey[i];
    else if (mode == 3) v = (i & 1) ? g_Tim[i >> 1] : g_Tre[i >> 1];
    else if (mode == 4) v = g_Tre[i];
    out[i] = v;
}

// ---------------------------------------------------------------------------
extern "C" void kernel_launch(void* const* d_in, const int* in_sizes, int n_in,
                              void* d_out, int out_size)
{
    if (n_in > 64) n_in = 64;
    bool used[64];
    for (int i = 0; i < 64; ++i) used[i] = false;
    auto take = [&](int sz) -> const float* {
        for (int i = 0; i < n_in; ++i)
            if (!used[i] && in_sizes[i] == sz) {
                used[i] = true;
                return (const float*)d_in[i];
            }
        return nullptr;
    };

    const float* hs = take(2304);
    const float* E0r; const float* E0i; int e0stride;
    {
        const float* a = take(E0_ELEMS);
        if (a) { E0r = a; E0i = take(E0_ELEMS); e0stride = 1; }
        else {
            const float* c1 = take(2 * E0_ELEMS);
            const float* c2 = take(2 * E0_ELEMS);
            if (c1 && c2)      { E0r = c1; E0i = c2;     e0stride = 2; }
            else if (c1)       { E0r = c1; E0i = c1 + 1; e0stride = 2; }
            else               { E0r = nullptr; E0i = nullptr; e0stride = 1; }
        }
    }
    const float* nW0 = take(128);
    const float* nb0 = take(128);
    const float* nW1 = take(16384);
    const float* nb1 = take(128);
    const float* nW2 = take(128);
    const float* nb2 = take(1);
    const float* eW0 = take(128);
    const float* eb0 = take(128);
    const float* eW1 = take(16384);
    const float* eb1 = take(128);
    const float* eW2 = take(1843200);
    const float* eb2 = take(14400);
    float* out = (float*)d_out;

    const bool fast = (out_size == EY_ELEMS + NN);   // confirmed in round 4

    prep_kernel<<<(NCOLS + 255) / 256, 256>>>();
    mlp_kernel<<<NN, 128>>>(hs, nW0, nb0, nW1, nb1, nW2, nb2,
                            eW0, eb0, eW1, eb1);
    wpack_kernel<<<(KP * NCOLS + 255) / 256, 256>>>(eW2);
    hfrag_kernel<<<NMG, 256>>>();

    gemm_mma<<<dim3(NCOLS / GN, NN / GM), 256>>>(eb2, fast ? out : nullptr);

    esum_kernel<<<NN, 256>>>(fast ? out : nullptr, E0r, E0i, e0stride,
                             fast ? out + EY_ELEMS : nullptr);

    if (!fast) {
        long long cnt; int mode;
        if      (out_size == EY_ELEMS + 2 * NN) { mode = 1; cnt = out_size; }
        else if (out_size == EY_ELEMS)          { mode = 2; cnt = out_size; }
        else if (out_size == 2 * NN)            { mode = 3; cnt = out_size; }
        else if (out_size == NN)                { mode = 4; cnt = out_size; }
        else { mode = 5; cnt = out_size / 4; }
        if (cnt < 1) cnt = 1;
        pack_kernel<<<(unsigned)((cnt + 255) / 256), 256>>>(out, cnt, mode);
    }
}